// round 1
// baseline (speedup 1.0000x reference)
#include <cuda_runtime.h>
#include <cuda_bf16.h>
#include <math.h>

#define DEV_INLINE __device__ __forceinline__

// Problem constants
constexpr int B_SZ  = 4;
constexpr int L_SZ  = 2048;
constexpr int DM    = 1024;           // d_model
constexpr int DI    = 2048;           // d_inner
constexpr int DS    = 16;             // d_state
constexpr int DTR   = 64;             // dt_rank
constexpr int NROWS = B_SZ * L_SZ;    // 8192
constexpr int DBC_W = DTR + 2 * DS;   // 96

// Scratch (device globals: no allocation allowed in kernel_launch)
__device__ float g_xn [NROWS * DM];        // 33.5 MB
__device__ float g_xz [NROWS * 2 * DI];    // 134 MB
__device__ float g_xc [NROWS * DI];        // 67 MB
__device__ float g_dbc[NROWS * DBC_W];     // 3.1 MB
__device__ float g_dt [NROWS * DI];        // 67 MB
__device__ float g_yp [NROWS * DI];        // 67 MB

DEV_INLINE float softplus_f(float v) {
    return v > 20.f ? v : log1pf(__expf(v));
}

// ---------------------------------------------------------------------------
// LayerNorm: one block per row of 1024, 256 threads, float4 per thread
// ---------------------------------------------------------------------------
__global__ __launch_bounds__(256)
void ln_kernel(const float* __restrict__ x, const float* __restrict__ g,
               const float* __restrict__ b, float* __restrict__ xn) {
    int row = blockIdx.x;
    int tid = threadIdx.x;
    const float4* xr = reinterpret_cast<const float4*>(x + (size_t)row * DM);
    float4 v = xr[tid];
    float s  = v.x + v.y + v.z + v.w;
    float sq = v.x * v.x + v.y * v.y + v.z * v.z + v.w * v.w;
    #pragma unroll
    for (int o = 16; o; o >>= 1) {
        s  += __shfl_xor_sync(0xffffffffu, s,  o);
        sq += __shfl_xor_sync(0xffffffffu, sq, o);
    }
    __shared__ float ss[8], ssq[8];
    int w = tid >> 5, lane = tid & 31;
    if (lane == 0) { ss[w] = s; ssq[w] = sq; }
    __syncthreads();
    if (w == 0) {
        s  = (lane < 8) ? ss[lane]  : 0.f;
        sq = (lane < 8) ? ssq[lane] : 0.f;
        #pragma unroll
        for (int o = 4; o; o >>= 1) {
            s  += __shfl_xor_sync(0xffffffffu, s,  o);
            sq += __shfl_xor_sync(0xffffffffu, sq, o);
        }
        if (lane == 0) { ss[0] = s; ssq[0] = sq; }
    }
    __syncthreads();
    float mu   = ss[0]  * (1.f / DM);
    float var  = ssq[0] * (1.f / DM) - mu * mu;
    float rstd = rsqrtf(var + 1e-5f);
    float4 gv = reinterpret_cast<const float4*>(g)[tid];
    float4 bv = reinterpret_cast<const float4*>(b)[tid];
    float4 o;
    o.x = (v.x - mu) * rstd * gv.x + bv.x;
    o.y = (v.y - mu) * rstd * gv.y + bv.y;
    o.z = (v.z - mu) * rstd * gv.z + bv.z;
    o.w = (v.w - mu) * rstd * gv.w + bv.w;
    reinterpret_cast<float4*>(xn + (size_t)row * DM)[tid] = o;
}

// ---------------------------------------------------------------------------
// SIMT fp32 GEMM: C[M,N] = A[M,K] @ B[K,N]  (row-major, explicit ld*)
//   BM=BN=128, BK=16, 256 threads, 8x8 per thread
//   EPI: 0=none, 1=softplus(acc + bias[col]), 2=acc + extra[row*ldc+col]
// ---------------------------------------------------------------------------
template<bool GUARD, int EPI>
__global__ __launch_bounds__(256)
void gemm_kernel(const float* __restrict__ A, const float* __restrict__ Bm,
                 float* __restrict__ C, int M, int N, int K,
                 int lda, int ldb, int ldc,
                 const float* __restrict__ extra) {
    constexpr int BM = 128, BN = 128, BK = 16, TM = 8, TN = 8;
    __shared__ float As[BK][BM + 8];
    __shared__ float Bs[BK][BN];
    int tid = threadIdx.x;
    int bm = blockIdx.y * BM, bn = blockIdx.x * BN;
    int tx = tid & 15, ty = tid >> 4;

    float acc[TM][TN] = {};

    int arow  = tid >> 2;         // 0..63
    int acol4 = (tid & 3) * 4;    // 0,4,8,12
    int brow  = tid >> 5;         // 0..7
    int bcol4 = (tid & 31) * 4;   // 0..124

    for (int k0 = 0; k0 < K; k0 += BK) {
        #pragma unroll
        for (int p = 0; p < 2; ++p) {
            int r = arow + p * 64;
            float4 v = make_float4(0.f, 0.f, 0.f, 0.f);
            if (!GUARD || (bm + r < M))
                v = *reinterpret_cast<const float4*>(A + (size_t)(bm + r) * lda + k0 + acol4);
            As[acol4 + 0][r] = v.x;
            As[acol4 + 1][r] = v.y;
            As[acol4 + 2][r] = v.z;
            As[acol4 + 3][r] = v.w;
        }
        #pragma unroll
        for (int p = 0; p < 2; ++p) {
            int r = brow + p * 8;
            float4 v = make_float4(0.f, 0.f, 0.f, 0.f);
            if (!GUARD || (bn + bcol4 < N))
                v = *reinterpret_cast<const float4*>(Bm + (size_t)(k0 + r) * ldb + bn + bcol4);
            *reinterpret_cast<float4*>(&Bs[r][bcol4]) = v;
        }
        __syncthreads();
        #pragma unroll
        for (int kk = 0; kk < BK; ++kk) {
            float af[TM], bf[TN];
            #pragma unroll
            for (int i = 0; i < TM; i += 4)
                *reinterpret_cast<float4*>(&af[i]) =
                    *reinterpret_cast<const float4*>(&As[kk][ty * TM + i]);
            #pragma unroll
            for (int j = 0; j < TN; j += 4)
                *reinterpret_cast<float4*>(&bf[j]) =
                    *reinterpret_cast<const float4*>(&Bs[kk][tx * TN + j]);
            #pragma unroll
            for (int i = 0; i < TM; ++i)
                #pragma unroll
                for (int j = 0; j < TN; ++j)
                    acc[i][j] = fmaf(af[i], bf[j], acc[i][j]);
        }
        __syncthreads();
    }

    #pragma unroll
    for (int i = 0; i < TM; ++i) {
        int row = bm + ty * TM + i;
        if (GUARD && row >= M) continue;
        #pragma unroll
        for (int j = 0; j < TN; j += 4) {
            int col = bn + tx * TN + j;
            if (GUARD && col >= N) continue;
            float4 v = *reinterpret_cast<float4*>(&acc[i][j]);
            if (EPI == 1) {
                float4 bb = *reinterpret_cast<const float4*>(extra + col);
                v.x = softplus_f(v.x + bb.x);
                v.y = softplus_f(v.y + bb.y);
                v.z = softplus_f(v.z + bb.z);
                v.w = softplus_f(v.w + bb.w);
            } else if (EPI == 2) {
                float4 r4 = *reinterpret_cast<const float4*>(extra + (size_t)row * ldc + col);
                v.x += r4.x; v.y += r4.y; v.z += r4.z; v.w += r4.w;
            }
            *reinterpret_cast<float4*>(C + (size_t)row * ldc + col) = v;
        }
    }
}

// ---------------------------------------------------------------------------
// Causal depthwise conv (k=4) + SiLU.  xh = xz[..., :DI]
// ---------------------------------------------------------------------------
__global__ __launch_bounds__(256)
void conv_silu_kernel(const float* __restrict__ xz, const float* __restrict__ w,
                      const float* __restrict__ bias, float* __restrict__ xc) {
    int idx = blockIdx.x * 256 + threadIdx.x;
    if (idx >= NROWS * DI) return;
    int row = idx >> 11;          // DI = 2048
    int d   = idx & (DI - 1);
    int t   = row & (L_SZ - 1);   // L = 2048
    float acc = bias[d];
    #pragma unroll
    for (int k = 0; k < 4; ++k) {
        int ts = t - 3 + k;
        if (ts >= 0)
            acc = fmaf(xz[(size_t)(row - 3 + k) * (2 * DI) + d], w[d * 4 + k], acc);
    }
    xc[idx] = acc / (1.f + __expf(-acc));     // silu
}

// ---------------------------------------------------------------------------
// Selective scan, fused with (+ D*u) * silu(z)
//   block: 128 threads = 32 channels x 4 state-groups (4 states each)
//   lane = c*4 + g  (c = channel-in-warp 0..7, g = state group 0..3)
//   chunked SMEM staging of dt/u/z/B/C (32 steps per chunk)
// ---------------------------------------------------------------------------
__global__ __launch_bounds__(128)
void scan_kernel(const float* __restrict__ dt, const float* __restrict__ dbc,
                 const float* __restrict__ xc, const float* __restrict__ xz,
                 const float* __restrict__ A_log, const float* __restrict__ Dp,
                 float* __restrict__ yp) {
    constexpr int CH = 32;
    int b   = blockIdx.y;
    int d0  = blockIdx.x * 32;
    int tid = threadIdx.x;
    int w = tid >> 5, lane = tid & 31, c = lane >> 2, g = lane & 3;
    int d = d0 + w * 8 + c;
    int lcol = w * 8 + c;

    __shared__ float s_dt[CH][32], s_u[CH][32], s_z[CH][32], s_bc[CH][32], s_y[CH][32];

    float An[4];
    #pragma unroll
    for (int j = 0; j < 4; ++j) An[j] = -__expf(A_log[d * DS + g * 4 + j]);
    float Dd = Dp[d];
    float h0 = 0.f, h1 = 0.f, h2 = 0.f, h3 = 0.f;

    for (int c0 = 0; c0 < L_SZ; c0 += CH) {
        for (int i = tid; i < CH * 32; i += 128) {
            int r = i >> 5, cc = i & 31;
            size_t row = (size_t)(b * L_SZ + c0 + r);
            s_dt[r][cc] = dt[row * DI + d0 + cc];
            s_u [r][cc] = xc[row * DI + d0 + cc];
            s_z [r][cc] = xz[row * (2 * DI) + DI + d0 + cc];
            s_bc[r][cc] = dbc[row * DBC_W + DTR + cc];
        }
        __syncthreads();
        #pragma unroll 4
        for (int r = 0; r < CH; ++r) {
            float dtv = s_dt[r][lcol];
            float uv  = s_u[r][lcol];
            float4 Bv = *reinterpret_cast<const float4*>(&s_bc[r][g * 4]);
            float4 Cv = *reinterpret_cast<const float4*>(&s_bc[r][16 + g * 4]);
            float dtu = dtv * uv;
            float dA0 = __expf(dtv * An[0]);
            float dA1 = __expf(dtv * An[1]);
            float dA2 = __expf(dtv * An[2]);
            float dA3 = __expf(dtv * An[3]);
            h0 = fmaf(dA0, h0, Bv.x * dtu);
            h1 = fmaf(dA1, h1, Bv.y * dtu);
            h2 = fmaf(dA2, h2, Bv.z * dtu);
            h3 = fmaf(dA3, h3, Bv.w * dtu);
            float ys = h0 * Cv.x;
            ys = fmaf(h1, Cv.y, ys);
            ys = fmaf(h2, Cv.z, ys);
            ys = fmaf(h3, Cv.w, ys);
            ys += __shfl_xor_sync(0xffffffffu, ys, 1);
            ys += __shfl_xor_sync(0xffffffffu, ys, 2);
            if (g == 0) {
                float z = s_z[r][lcol];
                s_y[r][lcol] = (ys + Dd * uv) * (z / (1.f + __expf(-z)));
            }
        }
        __syncthreads();
        for (int i = tid; i < CH * 32; i += 128) {
            int r = i >> 5, cc = i & 31;
            yp[(size_t)(b * L_SZ + c0 + r) * DI + d0 + cc] = s_y[r][cc];
        }
        // next-iteration load is separated from this compute by the barrier above;
        // store reads s_y only, next load writes s_dt/s_u/s_z/s_bc only.
    }
}

// ---------------------------------------------------------------------------
// kernel_launch
// ---------------------------------------------------------------------------
extern "C" void kernel_launch(void* const* d_in, const int* in_sizes, int n_in,
                              void* d_out, int out_size) {
    const float* x      = (const float*)d_in[0];
    const float* ln_g   = (const float*)d_in[1];
    const float* ln_b   = (const float*)d_in[2];
    const float* W_in   = (const float*)d_in[3];
    const float* conv_w = (const float*)d_in[4];
    const float* conv_b = (const float*)d_in[5];
    const float* W_x    = (const float*)d_in[6];
    const float* W_dt   = (const float*)d_in[7];
    const float* b_dt   = (const float*)d_in[8];
    const float* A_log  = (const float*)d_in[9];
    const float* Dp     = (const float*)d_in[10];
    const float* W_out  = (const float*)d_in[11];
    float* out = (float*)d_out;

    float *xn, *xz, *xc, *dbc, *dtb, *ypb;
    cudaGetSymbolAddress((void**)&xn,  g_xn);
    cudaGetSymbolAddress((void**)&xz,  g_xz);
    cudaGetSymbolAddress((void**)&xc,  g_xc);
    cudaGetSymbolAddress((void**)&dbc, g_dbc);
    cudaGetSymbolAddress((void**)&dtb, g_dt);
    cudaGetSymbolAddress((void**)&ypb, g_yp);

    // 1. LayerNorm
    ln_kernel<<<NROWS, 256>>>(x, ln_g, ln_b, xn);

    // 2. xz = xn @ W_in   [8192,1024]x[1024,4096]
    gemm_kernel<false, 0><<<dim3(4096 / 128, NROWS / 128), 256>>>(
        xn, W_in, xz, NROWS, 4096, DM, DM, 4096, 4096, nullptr);

    // 3. xc = silu(depthwise_conv(xh))
    conv_silu_kernel<<<(NROWS * DI) / 256, 256>>>(xz, conv_w, conv_b, xc);

    // 4. dbc = xc @ W_x   [8192,2048]x[2048,96]  (guarded: N=96)
    gemm_kernel<true, 0><<<dim3(1, NROWS / 128), 256>>>(
        xc, W_x, dbc, NROWS, DBC_W, DI, DI, DBC_W, DBC_W, nullptr);

    // 5. dt = softplus(dbc[:, :64] @ W_dt + b_dt)  [8192,64]x[64,2048]
    gemm_kernel<false, 1><<<dim3(DI / 128, NROWS / 128), 256>>>(
        dbc, W_dt, dtb, NROWS, DI, DTR, DBC_W, DI, DI, b_dt);

    // 6. selective scan + (+D*u)*silu(z)  -> yp
    scan_kernel<<<dim3(DI / 32, B_SZ), 128>>>(dtb, dbc, xc, xz, A_log, Dp, ypb);

    // 7. out = x + yp @ W_out  [8192,2048]x[2048,1024]
    gemm_kernel<false, 2><<<dim3(DM / 128, NROWS / 128), 256>>>(
        ypb, W_out, out, NROWS, DM, DI, DI, DM, DM, x);
}

// round 3
// speedup vs baseline: 2.2224x; 2.2224x over previous
#include <cuda_runtime.h>
#include <cuda_bf16.h>
#include <math.h>
#include <stdint.h>

#define DEV_INLINE __device__ __forceinline__

// Problem constants
constexpr int B_SZ  = 4;
constexpr int L_SZ  = 2048;
constexpr int DM    = 1024;           // d_model
constexpr int DI    = 2048;           // d_inner
constexpr int DS    = 16;             // d_state
constexpr int DTR   = 64;             // dt_rank
constexpr int NROWS = B_SZ * L_SZ;    // 8192
constexpr int DBC_W = DTR + 2 * DS;   // 96

// Scratch (device globals: no allocation allowed in kernel_launch)
__device__ float g_xn [NROWS * DM];
__device__ float g_xz [NROWS * 2 * DI];
__device__ float g_xc [NROWS * DI];
__device__ float g_dbc[NROWS * DBC_W];
__device__ float g_dt [NROWS * DI];
__device__ float g_yp [NROWS * DI];
// transposed weights (B operands, [N,K] row-major, tf32-rounded)
__device__ float g_wt_in [4096 * 1024];
__device__ float g_wt_x  [128 * 2048];   // padded 96->128 rows, zero-filled
__device__ float g_wt_dt [2048 * 64];
__device__ float g_wt_out[1024 * 2048];

DEV_INLINE float softplus_f(float v) {
    return v > 20.f ? v : log1pf(__expf(v));
}
// round-to-nearest tf32 (keeps mma.sync errors zero-mean; raw truncation would
// accumulate ~sqrt(K)*2^-10 correlated bias and fail the 1e-3 gate)
DEV_INLINE float to_tf32(float x) {
    uint32_t o;
    asm("cvt.rna.tf32.f32 %0, %1;" : "=r"(o) : "f"(x));
    return __uint_as_float(o);
}
DEV_INLINE uint32_t smem_u32(const void* p) {
    uint32_t a;
    asm("{ .reg .u64 t; cvta.to.shared.u64 t, %1; cvt.u32.u64 %0, t; }"
        : "=r"(a) : "l"(p));
    return a;
}
DEV_INLINE void cp_async16(uint32_t dst, const void* src) {
    asm volatile("cp.async.cg.shared.global [%0], [%1], 16;" :: "r"(dst), "l"(src));
}
#define CP_COMMIT() asm volatile("cp.async.commit_group;" ::: "memory")
#define CP_WAIT(n)  asm volatile("cp.async.wait_group %0;" :: "n"(n) : "memory")

DEV_INLINE void mma_tf32(float* d, const float* a, const float* b) {
    asm volatile(
        "mma.sync.aligned.m16n8k8.row.col.f32.tf32.tf32.f32 "
        "{%0,%1,%2,%3}, {%4,%5,%6,%7}, {%8,%9}, {%0,%1,%2,%3};"
        : "+f"(d[0]), "+f"(d[1]), "+f"(d[2]), "+f"(d[3])
        : "r"(__float_as_uint(a[0])), "r"(__float_as_uint(a[1])),
          "r"(__float_as_uint(a[2])), "r"(__float_as_uint(a[3])),
          "r"(__float_as_uint(b[0])), "r"(__float_as_uint(b[1])));
}

// ===========================================================================
// Tensor-core tf32 GEMM: C[M,N] = A[M,K] @ Bt[N,K]^T  (both K-major)
//   BM=BN=128, BK=32, 256 threads, 8 warps (2x4), warp tile 64x32
//   cp.async double-buffered; smem rows stride 36 floats (conflict-free frags)
//   EPI: 0=store, 1=softplus(acc+bias[col]), 2=acc+extra[row*ldc+col]
//   ROUND: tf32-round outputs (when output feeds another GEMM's A operand)
// ===========================================================================
constexpr int KSTR = 36;                       // smem row stride (floats)
constexpr int TILE_F = 128 * KSTR;             // floats per operand tile
constexpr int GEMM_SMEM_BYTES = 2 * 2 * TILE_F * 4;   // 73728

template<int EPI, int ROUND>
__global__ __launch_bounds__(256, 2)
void mma_gemm(const float* __restrict__ A, const float* __restrict__ Bt,
              float* __restrict__ C, int K, int lda, int ldb, int ldc,
              int Nstore, const float* __restrict__ extra) {
    extern __shared__ float smem[];
    const int tid = threadIdx.x;
    const int bm = blockIdx.y * 128, bn = blockIdx.x * 128;
    const int lane = tid & 31, wid = tid >> 5;
    const int g = lane >> 2, tig = lane & 3;
    const int wr = (wid & 1) * 64;        // warp M offset
    const int wc = (wid >> 1) * 32;       // warp N offset

    const uint32_t sb = smem_u32(smem);
    const int r8 = tid >> 3, c4 = (tid & 7) * 4;   // loader: 8 float4 per row

    auto issue_tile = [&](int kc, int buf) {
        const float* asrc = A  + (size_t)(bm + r8) * lda + kc * 32 + c4;
        const float* bsrc = Bt + (size_t)(bn + r8) * ldb + kc * 32 + c4;
        uint32_t abase = sb + (buf * 2 * TILE_F) * 4;
        uint32_t bbase = abase + TILE_F * 4;
        #pragma unroll
        for (int p = 0; p < 4; ++p) {
            cp_async16(abase + ((r8 + p * 32) * KSTR + c4) * 4,
                       asrc + (size_t)(p * 32) * lda);
            cp_async16(bbase + ((r8 + p * 32) * KSTR + c4) * 4,
                       bsrc + (size_t)(p * 32) * ldb);
        }
    };

    float acc[4][4][4] = {};
    const int nch = K >> 5;

    issue_tile(0, 0);
    CP_COMMIT();

    for (int i = 0; i < nch; ++i) {
        const int b = i & 1;
        if (i + 1 < nch) {
            issue_tile(i + 1, b ^ 1);
            CP_COMMIT();
            CP_WAIT(1);
        } else {
            CP_WAIT(0);
        }
        __syncthreads();
        const float* As = smem + b * 2 * TILE_F;
        const float* Bs = As + TILE_F;
        #pragma unroll
        for (int ks = 0; ks < 4; ++ks) {
            const int kk = ks * 8 + tig;
            float af[4][4], bf[4][2];
            #pragma unroll
            for (int mi = 0; mi < 4; ++mi) {
                int r0 = wr + mi * 16 + g;
                af[mi][0] = As[r0 * KSTR + kk];
                af[mi][1] = As[(r0 + 8) * KSTR + kk];
                af[mi][2] = As[r0 * KSTR + kk + 4];
                af[mi][3] = As[(r0 + 8) * KSTR + kk + 4];
            }
            #pragma unroll
            for (int ni = 0; ni < 4; ++ni) {
                int rb = wc + ni * 8 + g;
                bf[ni][0] = Bs[rb * KSTR + kk];
                bf[ni][1] = Bs[rb * KSTR + kk + 4];
            }
            #pragma unroll
            for (int mi = 0; mi < 4; ++mi)
                #pragma unroll
                for (int ni = 0; ni < 4; ++ni)
                    mma_tf32(acc[mi][ni], af[mi], bf[ni]);
        }
        __syncthreads();
    }

    // Epilogue: each thread owns 2 rows x 1 float2 per (mi,ni) fragment
    #pragma unroll
    for (int mi = 0; mi < 4; ++mi) {
        #pragma unroll
        for (int half = 0; half < 2; ++half) {
            const int row = bm + wr + mi * 16 + g + half * 8;
            #pragma unroll
            for (int ni = 0; ni < 4; ++ni) {
                const int col = bn + wc + ni * 8 + 2 * tig;
                if (col >= Nstore) continue;
                float2 v = make_float2(acc[mi][ni][half * 2],
                                       acc[mi][ni][half * 2 + 1]);
                if (EPI == 1) {
                    float2 bb = *reinterpret_cast<const float2*>(extra + col);
                    v.x = softplus_f(v.x + bb.x);
                    v.y = softplus_f(v.y + bb.y);
                } else if (EPI == 2) {
                    float2 rr = *reinterpret_cast<const float2*>(
                        extra + (size_t)row * ldc + col);
                    v.x += rr.x; v.y += rr.y;
                }
                if (ROUND) { v.x = to_tf32(v.x); v.y = to_tf32(v.y); }
                *reinterpret_cast<float2*>(C + (size_t)row * ldc + col) = v;
            }
        }
    }
}

// ===========================================================================
// Weight transpose (fp32->tf32): dst[c][r] = tf32(src[r][c]), zero pad rows
// ===========================================================================
__global__ __launch_bounds__(1024)
void transpose_pad_kernel(const float* __restrict__ src, float* __restrict__ dst,
                          int R, int Ccols) {
    __shared__ float t[32][33];
    int r0 = blockIdx.x * 32, c0 = blockIdx.y * 32;
    int tx = threadIdx.x, ty = threadIdx.y;
    int c = c0 + tx;
    float v = 0.f;
    if (c < Ccols) v = to_tf32(src[(size_t)(r0 + ty) * Ccols + c]);
    t[ty][tx] = v;
    __syncthreads();
    dst[(size_t)(c0 + ty) * R + r0 + tx] = t[tx][ty];
}

// ---------------------------------------------------------------------------
// LayerNorm (output tf32-rounded: feeds GEMM1 A)
// ---------------------------------------------------------------------------
__global__ __launch_bounds__(256)
void ln_kernel(const float* __restrict__ x, const float* __restrict__ g,
               const float* __restrict__ b, float* __restrict__ xn) {
    int row = blockIdx.x;
    int tid = threadIdx.x;
    const float4* xr = reinterpret_cast<const float4*>(x + (size_t)row * DM);
    float4 v = xr[tid];
    float s  = v.x + v.y + v.z + v.w;
    float sq = v.x * v.x + v.y * v.y + v.z * v.z + v.w * v.w;
    #pragma unroll
    for (int o = 16; o; o >>= 1) {
        s  += __shfl_xor_sync(0xffffffffu, s,  o);
        sq += __shfl_xor_sync(0xffffffffu, sq, o);
    }
    __shared__ float ss[8], ssq[8];
    int w = tid >> 5, lane = tid & 31;
    if (lane == 0) { ss[w] = s; ssq[w] = sq; }
    __syncthreads();
    if (w == 0) {
        s  = (lane < 8) ? ss[lane]  : 0.f;
        sq = (lane < 8) ? ssq[lane] : 0.f;
        #pragma unroll
        for (int o = 4; o; o >>= 1) {
            s  += __shfl_xor_sync(0xffffffffu, s,  o);
            sq += __shfl_xor_sync(0xffffffffu, sq, o);
        }
        if (lane == 0) { ss[0] = s; ssq[0] = sq; }
    }
    __syncthreads();
    float mu   = ss[0]  * (1.f / DM);
    float var  = ssq[0] * (1.f / DM) - mu * mu;
    float rstd = rsqrtf(var + 1e-5f);
    float4 gv = reinterpret_cast<const float4*>(g)[tid];
    float4 bv = reinterpret_cast<const float4*>(b)[tid];
    float4 o;
    o.x = to_tf32((v.x - mu) * rstd * gv.x + bv.x);
    o.y = to_tf32((v.y - mu) * rstd * gv.y + bv.y);
    o.z = to_tf32((v.z - mu) * rstd * gv.z + bv.z);
    o.w = to_tf32((v.w - mu) * rstd * gv.w + bv.w);
    reinterpret_cast<float4*>(xn + (size_t)row * DM)[tid] = o;
}

// ---------------------------------------------------------------------------
// Causal depthwise conv (k=4) + SiLU (output tf32-rounded: feeds GEMM2 A)
// ---------------------------------------------------------------------------
__global__ __launch_bounds__(256)
void conv_silu_kernel(const float* __restrict__ xz, const float* __restrict__ w,
                      const float* __restrict__ bias, float* __restrict__ xc) {
    int idx = blockIdx.x * 256 + threadIdx.x;
    if (idx >= NROWS * DI) return;
    int row = idx >> 11;          // DI = 2048
    int d   = idx & (DI - 1);
    int t   = row & (L_SZ - 1);   // L = 2048
    float acc = bias[d];
    #pragma unroll
    for (int k = 0; k < 4; ++k) {
        int ts = t - 3 + k;
        if (ts >= 0)
            acc = fmaf(xz[(size_t)(row - 3 + k) * (2 * DI) + d], w[d * 4 + k], acc);
    }
    xc[idx] = to_tf32(acc / (1.f + __expf(-acc)));     // silu
}

// ---------------------------------------------------------------------------
// Selective scan, fused with (+ D*u) * silu(z)  (yp tf32-rounded: feeds GEMM4)
// ---------------------------------------------------------------------------
__global__ __launch_bounds__(128)
void scan_kernel(const float* __restrict__ dt, const float* __restrict__ dbc,
                 const float* __restrict__ xc, const float* __restrict__ xz,
                 const float* __restrict__ A_log, const float* __restrict__ Dp,
                 float* __restrict__ yp) {
    constexpr int CH = 32;
    int b   = blockIdx.y;
    int d0  = blockIdx.x * 32;
    int tid = threadIdx.x;
    int w = tid >> 5, lane = tid & 31, c = lane >> 2, g = lane & 3;
    int d = d0 + w * 8 + c;
    int lcol = w * 8 + c;

    __shared__ float s_dt[CH][32], s_u[CH][32], s_z[CH][32], s_bc[CH][32], s_y[CH][32];

    float An[4];
    #pragma unroll
    for (int j = 0; j < 4; ++j) An[j] = -__expf(A_log[d * DS + g * 4 + j]);
    float Dd = Dp[d];
    float h0 = 0.f, h1 = 0.f, h2 = 0.f, h3 = 0.f;

    for (int c0 = 0; c0 < L_SZ; c0 += CH) {
        for (int i = tid; i < CH * 32; i += 128) {
            int r = i >> 5, cc = i & 31;
            size_t row = (size_t)(b * L_SZ + c0 + r);
            s_dt[r][cc] = dt[row * DI + d0 + cc];
            s_u [r][cc] = xc[row * DI + d0 + cc];
            s_z [r][cc] = xz[row * (2 * DI) + DI + d0 + cc];
            s_bc[r][cc] = dbc[row * DBC_W + DTR + cc];
        }
        __syncthreads();
        #pragma unroll 4
        for (int r = 0; r < CH; ++r) {
            float dtv = s_dt[r][lcol];
            float uv  = s_u[r][lcol];
            float4 Bv = *reinterpret_cast<const float4*>(&s_bc[r][g * 4]);
            float4 Cv = *reinterpret_cast<const float4*>(&s_bc[r][16 + g * 4]);
            float dtu = dtv * uv;
            float dA0 = __expf(dtv * An[0]);
            float dA1 = __expf(dtv * An[1]);
            float dA2 = __expf(dtv * An[2]);
            float dA3 = __expf(dtv * An[3]);
            h0 = fmaf(dA0, h0, Bv.x * dtu);
            h1 = fmaf(dA1, h1, Bv.y * dtu);
            h2 = fmaf(dA2, h2, Bv.z * dtu);
            h3 = fmaf(dA3, h3, Bv.w * dtu);
            float ys = h0 * Cv.x;
            ys = fmaf(h1, Cv.y, ys);
            ys = fmaf(h2, Cv.z, ys);
            ys = fmaf(h3, Cv.w, ys);
            ys += __shfl_xor_sync(0xffffffffu, ys, 1);
            ys += __shfl_xor_sync(0xffffffffu, ys, 2);
            if (g == 0) {
                float z = s_z[r][lcol];
                s_y[r][lcol] = to_tf32((ys + Dd * uv) * (z / (1.f + __expf(-z))));
            }
        }
        __syncthreads();
        for (int i = tid; i < CH * 32; i += 128) {
            int r = i >> 5, cc = i & 31;
            yp[(size_t)(b * L_SZ + c0 + r) * DI + d0 + cc] = s_y[r][cc];
        }
    }
}

// ---------------------------------------------------------------------------
// kernel_launch
// ---------------------------------------------------------------------------
extern "C" void kernel_launch(void* const* d_in, const int* in_sizes, int n_in,
                              void* d_out, int out_size) {
    const float* x      = (const float*)d_in[0];
    const float* ln_g   = (const float*)d_in[1];
    const float* ln_b   = (const float*)d_in[2];
    const float* W_in   = (const float*)d_in[3];
    const float* conv_w = (const float*)d_in[4];
    const float* conv_b = (const float*)d_in[5];
    const float* W_x    = (const float*)d_in[6];
    const float* W_dt   = (const float*)d_in[7];
    const float* b_dt   = (const float*)d_in[8];
    const float* A_log  = (const float*)d_in[9];
    const float* Dp     = (const float*)d_in[10];
    const float* W_out  = (const float*)d_in[11];
    float* out = (float*)d_out;

    float *xn, *xz, *xc, *dbc, *dtb, *ypb, *wtin, *wtx, *wtdt, *wtout;
    cudaGetSymbolAddress((void**)&xn,    g_xn);
    cudaGetSymbolAddress((void**)&xz,    g_xz);
    cudaGetSymbolAddress((void**)&xc,    g_xc);
    cudaGetSymbolAddress((void**)&dbc,   g_dbc);
    cudaGetSymbolAddress((void**)&dtb,   g_dt);
    cudaGetSymbolAddress((void**)&ypb,   g_yp);
    cudaGetSymbolAddress((void**)&wtin,  g_wt_in);
    cudaGetSymbolAddress((void**)&wtx,   g_wt_x);
    cudaGetSymbolAddress((void**)&wtdt,  g_wt_dt);
    cudaGetSymbolAddress((void**)&wtout, g_wt_out);

    cudaFuncSetAttribute(mma_gemm<0,0>, cudaFuncAttributeMaxDynamicSharedMemorySize, GEMM_SMEM_BYTES);
    cudaFuncSetAttribute(mma_gemm<0,1>, cudaFuncAttributeMaxDynamicSharedMemorySize, GEMM_SMEM_BYTES);
    cudaFuncSetAttribute(mma_gemm<1,0>, cudaFuncAttributeMaxDynamicSharedMemorySize, GEMM_SMEM_BYTES);
    cudaFuncSetAttribute(mma_gemm<2,0>, cudaFuncAttributeMaxDynamicSharedMemorySize, GEMM_SMEM_BYTES);

    dim3 tb(32, 32);
    // W_in [1024,4096] -> wt_in [4096,1024]
    transpose_pad_kernel<<<dim3(1024 / 32, 4096 / 32), tb>>>(W_in, wtin, 1024, 4096);
    // W_x [2048,96] -> wt_x [128,2048] (rows 96..127 zero)
    transpose_pad_kernel<<<dim3(2048 / 32, 128 / 32), tb>>>(W_x, wtx, 2048, 96);
    // W_dt [64,2048] -> wt_dt [2048,64]
    transpose_pad_kernel<<<dim3(64 / 32, 2048 / 32), tb>>>(W_dt, wtdt, 64, 2048);
    // W_out [2048,1024] -> wt_out [1024,2048]
    transpose_pad_kernel<<<dim3(2048 / 32, 1024 / 32), tb>>>(W_out, wtout, 2048, 1024);

    // 1. LayerNorm
    ln_kernel<<<NROWS, 256>>>(x, ln_g, ln_b, xn);

    // 2. xz = xn @ W_in   [8192,1024] x [1024,4096]
    mma_gemm<0,0><<<dim3(4096 / 128, NROWS / 128), 256, GEMM_SMEM_BYTES>>>(
        xn, wtin, xz, DM, DM, DM, 4096, 4096, nullptr);

    // 3. xc = silu(depthwise_conv(xh))
    conv_silu_kernel<<<(NROWS * DI) / 256, 256>>>(xz, conv_w, conv_b, xc);

    // 4. dbc = xc @ W_x   [8192,2048] x [2048,96]  (N padded to 128, store 96;
    //    ROUND: dbc feeds GEMM3's A operand)
    mma_gemm<0,1><<<dim3(1, NROWS / 128), 256, GEMM_SMEM_BYTES>>>(
        xc, wtx, dbc, DI, DI, DI, DBC_W, DBC_W, nullptr);

    // 5. dt = softplus(dbc[:, :64] @ W_dt + b_dt)   [8192,64] x [64,2048]
    mma_gemm<1,0><<<dim3(DI / 128, NROWS / 128), 256, GEMM_SMEM_BYTES>>>(
        dbc, wtdt, dtb, DTR, DBC_W, DTR, DI, DI, b_dt);

    // 6. selective scan + (+D*u)*silu(z)  -> yp
    scan_kernel<<<dim3(DI / 32, B_SZ), 128>>>(dtb, dbc, xc, xz, A_log, Dp, ypb);

    // 7. out = x + yp @ W_out   [8192,2048] x [2048,1024]
    mma_gemm<2,0><<<dim3(DM / 128, NROWS / 128), 256, GEMM_SMEM_BYTES>>>(
        ypb, wtout, out, DI, DI, DI, DM, DM, x);
}

// round 4
// speedup vs baseline: 2.8801x; 1.2960x over previous
#include <cuda_runtime.h>
#include <cuda_bf16.h>
#include <math.h>
#include <stdint.h>

#define DEV_INLINE __device__ __forceinline__

// Problem constants
constexpr int B_SZ  = 4;
constexpr int L_SZ  = 2048;
constexpr int DM    = 1024;           // d_model
constexpr int DI    = 2048;           // d_inner
constexpr int DS    = 16;             // d_state
constexpr int DTR   = 64;             // dt_rank
constexpr int NROWS = B_SZ * L_SZ;    // 8192
constexpr int DBC_W = DTR + 2 * DS;   // 96

// Scratch (device globals: no allocation allowed in kernel_launch)
__device__ float g_xz [NROWS * 2 * DI];          // fp32: conv input + scan z
__device__ float g_xc [NROWS * DI];              // fp32: scan u
__device__ float g_dbc[NROWS * DBC_W];           // fp32: scan B/C
__device__ float g_dt [NROWS * DI];              // fp32: scan dt
// bf16 GEMM operands
__device__ __nv_bfloat16 g_xn16 [NROWS * DM];
__device__ __nv_bfloat16 g_xc16 [NROWS * DI];
__device__ __nv_bfloat16 g_dbc16[NROWS * DBC_W];
__device__ __nv_bfloat16 g_yp16 [NROWS * DI];
// transposed weights (B operands, [N,K] row-major, bf16)
__device__ __nv_bfloat16 g_wt_in [4096 * 1024];
__device__ __nv_bfloat16 g_wt_x  [128 * 2048];   // padded 96->128 rows, zeros
__device__ __nv_bfloat16 g_wt_dt [2048 * 64];
__device__ __nv_bfloat16 g_wt_out[1024 * 2048];

DEV_INLINE float softplus_f(float v) {
    return v > 20.f ? v : log1pf(__expf(v));
}
DEV_INLINE uint32_t smem_u32(const void* p) {
    uint32_t a;
    asm("{ .reg .u64 t; cvta.to.shared.u64 t, %1; cvt.u32.u64 %0, t; }"
        : "=r"(a) : "l"(p));
    return a;
}
DEV_INLINE void cp_async16(uint32_t dst, const void* src) {
    asm volatile("cp.async.cg.shared.global [%0], [%1], 16;" :: "r"(dst), "l"(src));
}
#define CP_COMMIT() asm volatile("cp.async.commit_group;" ::: "memory")
#define CP_WAIT(n)  asm volatile("cp.async.wait_group %0;" :: "n"(n) : "memory")

DEV_INLINE void ldsm_x4(uint32_t addr, uint32_t& r0, uint32_t& r1,
                        uint32_t& r2, uint32_t& r3) {
    asm volatile("ldmatrix.sync.aligned.m8n8.x4.shared.b16 {%0,%1,%2,%3}, [%4];"
                 : "=r"(r0), "=r"(r1), "=r"(r2), "=r"(r3) : "r"(addr));
}
DEV_INLINE void mma_bf16(float* d, const uint32_t* a, const uint32_t* b) {
    asm volatile(
        "mma.sync.aligned.m16n8k16.row.col.f32.bf16.bf16.f32 "
        "{%0,%1,%2,%3}, {%4,%5,%6,%7}, {%8,%9}, {%0,%1,%2,%3};"
        : "+f"(d[0]), "+f"(d[1]), "+f"(d[2]), "+f"(d[3])
        : "r"(a[0]), "r"(a[1]), "r"(a[2]), "r"(a[3]), "r"(b[0]), "r"(b[1]));
}

// ===========================================================================
// bf16 tensor-core GEMM: C[M,N] = A[M,K] @ Bt[N,K]^T
//   BM=BN=128, BK=32, 256 threads, 8 warps (2x4), warp tile 64x32
//   ldmatrix fragment loads; smem row stride 40 bf16 (conflict-free)
//   EPI: 0=store, 1=softplus(acc+bias[col]), 2=acc+extra[row*ldc+col]
//   ST2: also store bf16 copy to C2
// ===========================================================================
constexpr int KS2   = 40;                    // smem row stride (bf16)
constexpr int TILEB = 128 * KS2 * 2;         // bytes per operand tile = 10240
constexpr int GEMM_SMEM_BYTES = 2 * 2 * TILEB;  // 40960

template<int EPI, bool ST2>
__global__ __launch_bounds__(256, 2)
void mma_gemm(const __nv_bfloat16* __restrict__ A,
              const __nv_bfloat16* __restrict__ Bt,
              float* __restrict__ C, __nv_bfloat16* __restrict__ C2,
              int K, int lda, int ldb, int ldc, int Nstore,
              const float* __restrict__ extra) {
    extern __shared__ char smem[];
    const uint32_t sb = smem_u32(smem);
    const int tid = threadIdx.x;
    const int bm = blockIdx.y * 128, bn = blockIdx.x * 128;
    const int lane = tid & 31, wid = tid >> 5;
    const int g = lane >> 2, tig = lane & 3;
    const int wr = (wid & 1) * 64;        // warp M offset
    const int wc = (wid >> 1) * 32;       // warp N offset

    const int lr = tid >> 2;              // loader row 0..63
    const int lc = (tid & 3) * 8;         // bf16 col offset (8 bf16 = 16B)

    auto issue_tile = [&](int kc, int buf) {
        const __nv_bfloat16* as = A  + (size_t)(bm + lr) * lda + kc * 32 + lc;
        const __nv_bfloat16* bs = Bt + (size_t)(bn + lr) * ldb + kc * 32 + lc;
        uint32_t ab = sb + buf * 2 * TILEB;
        uint32_t bb = ab + TILEB;
        #pragma unroll
        for (int p = 0; p < 2; ++p) {
            cp_async16(ab + ((lr + p * 64) * KS2 + lc) * 2, as + (size_t)(p * 64) * lda);
            cp_async16(bb + ((lr + p * 64) * KS2 + lc) * 2, bs + (size_t)(p * 64) * ldb);
        }
    };

    // per-lane ldmatrix base offsets (bytes)
    const uint32_t a_lo = ((wr + (lane & 15)) * KS2 + ((lane >> 4) << 3)) * 2;
    const uint32_t b_lo = ((wc + (lane & 7) + ((lane >> 4) << 3)) * KS2
                           + (((lane >> 3) & 1) << 3)) * 2;

    float acc[4][4][4] = {};
    const int nch = K >> 5;

    issue_tile(0, 0);
    CP_COMMIT();

    for (int i = 0; i < nch; ++i) {
        const int b = i & 1;
        if (i + 1 < nch) {
            issue_tile(i + 1, b ^ 1);
            CP_COMMIT();
            CP_WAIT(1);
        } else {
            CP_WAIT(0);
        }
        __syncthreads();
        const uint32_t ab = sb + b * 2 * TILEB;
        const uint32_t bb = ab + TILEB;
        #pragma unroll
        for (int ks = 0; ks < 2; ++ks) {
            uint32_t af[4][4], bf[4][2];
            #pragma unroll
            for (int mi = 0; mi < 4; ++mi)
                ldsm_x4(ab + a_lo + (mi * 16 * KS2 + ks * 16) * 2,
                        af[mi][0], af[mi][1], af[mi][2], af[mi][3]);
            #pragma unroll
            for (int np = 0; np < 2; ++np) {
                uint32_t r0, r1, r2, r3;
                ldsm_x4(bb + b_lo + (np * 16 * KS2 + ks * 16) * 2, r0, r1, r2, r3);
                bf[np * 2][0] = r0; bf[np * 2][1] = r1;
                bf[np * 2 + 1][0] = r2; bf[np * 2 + 1][1] = r3;
            }
            #pragma unroll
            for (int mi = 0; mi < 4; ++mi)
                #pragma unroll
                for (int ni = 0; ni < 4; ++ni)
                    mma_bf16(acc[mi][ni], af[mi], bf[ni]);
        }
        __syncthreads();
    }

    // Epilogue
    #pragma unroll
    for (int mi = 0; mi < 4; ++mi) {
        #pragma unroll
        for (int half = 0; half < 2; ++half) {
            const int row = bm + wr + mi * 16 + g + half * 8;
            #pragma unroll
            for (int ni = 0; ni < 4; ++ni) {
                const int col = bn + wc + ni * 8 + 2 * tig;
                if (col >= Nstore) continue;
                float2 v = make_float2(acc[mi][ni][half * 2],
                                       acc[mi][ni][half * 2 + 1]);
                if (EPI == 1) {
                    float2 bb2 = *reinterpret_cast<const float2*>(extra + col);
                    v.x = softplus_f(v.x + bb2.x);
                    v.y = softplus_f(v.y + bb2.y);
                } else if (EPI == 2) {
                    float2 rr = *reinterpret_cast<const float2*>(
                        extra + (size_t)row * ldc + col);
                    v.x += rr.x; v.y += rr.y;
                }
                *reinterpret_cast<float2*>(C + (size_t)row * ldc + col) = v;
                if (ST2) {
                    __nv_bfloat162 h = __floats2bfloat162_rn(v.x, v.y);
                    *reinterpret_cast<__nv_bfloat162*>(C2 + (size_t)row * ldc + col) = h;
                }
            }
        }
    }
}

// ===========================================================================
// Weight transpose (fp32 -> bf16): dst[c][r] = bf16(src[r][c]), zero pad rows
// ===========================================================================
__global__ __launch_bounds__(1024)
void transpose_pad_kernel(const float* __restrict__ src,
                          __nv_bfloat16* __restrict__ dst, int R, int Ccols) {
    __shared__ float t[32][33];
    int r0 = blockIdx.x * 32, c0 = blockIdx.y * 32;
    int tx = threadIdx.x, ty = threadIdx.y;
    int c = c0 + tx;
    float v = 0.f;
    if (c < Ccols) v = src[(size_t)(r0 + ty) * Ccols + c];
    t[ty][tx] = v;
    __syncthreads();
    dst[(size_t)(c0 + ty) * R + r0 + tx] = __float2bfloat16_rn(t[tx][ty]);
}

// ---------------------------------------------------------------------------
// LayerNorm -> bf16 (only feeds GEMM1 A)
// ---------------------------------------------------------------------------
__global__ __launch_bounds__(256)
void ln_kernel(const float* __restrict__ x, const float* __restrict__ g,
               const float* __restrict__ b, __nv_bfloat16* __restrict__ xn16) {
    int row = blockIdx.x;
    int tid = threadIdx.x;
    const float4* xr = reinterpret_cast<const float4*>(x + (size_t)row * DM);
    float4 v = xr[tid];
    float s  = v.x + v.y + v.z + v.w;
    float sq = v.x * v.x + v.y * v.y + v.z * v.z + v.w * v.w;
    #pragma unroll
    for (int o = 16; o; o >>= 1) {
        s  += __shfl_xor_sync(0xffffffffu, s,  o);
        sq += __shfl_xor_sync(0xffffffffu, sq, o);
    }
    __shared__ float ss[8], ssq[8];
    int w = tid >> 5, lane = tid & 31;
    if (lane == 0) { ss[w] = s; ssq[w] = sq; }
    __syncthreads();
    if (w == 0) {
        s  = (lane < 8) ? ss[lane]  : 0.f;
        sq = (lane < 8) ? ssq[lane] : 0.f;
        #pragma unroll
        for (int o = 4; o; o >>= 1) {
            s  += __shfl_xor_sync(0xffffffffu, s,  o);
            sq += __shfl_xor_sync(0xffffffffu, sq, o);
        }
        if (lane == 0) { ss[0] = s; ssq[0] = sq; }
    }
    __syncthreads();
    float mu   = ss[0]  * (1.f / DM);
    float var  = ssq[0] * (1.f / DM) - mu * mu;
    float rstd = rsqrtf(var + 1e-5f);
    float4 gv = reinterpret_cast<const float4*>(g)[tid];
    float4 bv = reinterpret_cast<const float4*>(b)[tid];
    __nv_bfloat162 p0 = __floats2bfloat162_rn((v.x - mu) * rstd * gv.x + bv.x,
                                              (v.y - mu) * rstd * gv.y + bv.y);
    __nv_bfloat162 p1 = __floats2bfloat162_rn((v.z - mu) * rstd * gv.z + bv.z,
                                              (v.w - mu) * rstd * gv.w + bv.w);
    uint2 u;
    u.x = *reinterpret_cast<uint32_t*>(&p0);
    u.y = *reinterpret_cast<uint32_t*>(&p1);
    reinterpret_cast<uint2*>(xn16 + (size_t)row * DM)[tid] = u;
}

// ---------------------------------------------------------------------------
// Causal depthwise conv (k=4) + SiLU -> fp32 (scan u) + bf16 (GEMM2 A)
// ---------------------------------------------------------------------------
__global__ __launch_bounds__(256)
void conv_silu_kernel(const float* __restrict__ xz, const float* __restrict__ w,
                      const float* __restrict__ bias, float* __restrict__ xc,
                      __nv_bfloat16* __restrict__ xc16) {
    int idx = blockIdx.x * 256 + threadIdx.x;
    if (idx >= NROWS * DI) return;
    int row = idx >> 11;          // DI = 2048
    int d   = idx & (DI - 1);
    int t   = row & (L_SZ - 1);   // L = 2048
    float acc = bias[d];
    #pragma unroll
    for (int k = 0; k < 4; ++k) {
        int ts = t - 3 + k;
        if (ts >= 0)
            acc = fmaf(xz[(size_t)(row - 3 + k) * (2 * DI) + d], w[d * 4 + k], acc);
    }
    float o = acc / (1.f + __expf(-acc));     // silu
    xc[idx] = o;
    xc16[idx] = __float2bfloat16_rn(o);
}

// ---------------------------------------------------------------------------
// Selective scan, fused with (+ D*u) * silu(z); yp -> bf16 (GEMM4 A)
// ---------------------------------------------------------------------------
__global__ __launch_bounds__(128)
void scan_kernel(const float* __restrict__ dt, const float* __restrict__ dbc,
                 const float* __restrict__ xc, const float* __restrict__ xz,
                 const float* __restrict__ A_log, const float* __restrict__ Dp,
                 __nv_bfloat16* __restrict__ yp16) {
    constexpr int CH = 32;
    int b   = blockIdx.y;
    int d0  = blockIdx.x * 32;
    int tid = threadIdx.x;
    int w = tid >> 5, lane = tid & 31, c = lane >> 2, g = lane & 3;
    int d = d0 + w * 8 + c;
    int lcol = w * 8 + c;

    __shared__ float s_dt[CH][32], s_u[CH][32], s_z[CH][32], s_bc[CH][32], s_y[CH][32];

    float An[4];
    #pragma unroll
    for (int j = 0; j < 4; ++j) An[j] = -__expf(A_log[d * DS + g * 4 + j]);
    float Dd = Dp[d];
    float h0 = 0.f, h1 = 0.f, h2 = 0.f, h3 = 0.f;

    for (int c0 = 0; c0 < L_SZ; c0 += CH) {
        for (int i = tid; i < CH * 32; i += 128) {
            int r = i >> 5, cc = i & 31;
            size_t row = (size_t)(b * L_SZ + c0 + r);
            s_dt[r][cc] = dt[row * DI + d0 + cc];
            s_u [r][cc] = xc[row * DI + d0 + cc];
            s_z [r][cc] = xz[row * (2 * DI) + DI + d0 + cc];
            s_bc[r][cc] = dbc[row * DBC_W + DTR + cc];
        }
        __syncthreads();
        #pragma unroll 4
        for (int r = 0; r < CH; ++r) {
            float dtv = s_dt[r][lcol];
            float uv  = s_u[r][lcol];
            float4 Bv = *reinterpret_cast<const float4*>(&s_bc[r][g * 4]);
            float4 Cv = *reinterpret_cast<const float4*>(&s_bc[r][16 + g * 4]);
            float dtu = dtv * uv;
            float dA0 = __expf(dtv * An[0]);
            float dA1 = __expf(dtv * An[1]);
            float dA2 = __expf(dtv * An[2]);
            float dA3 = __expf(dtv * An[3]);
            h0 = fmaf(dA0, h0, Bv.x * dtu);
            h1 = fmaf(dA1, h1, Bv.y * dtu);
            h2 = fmaf(dA2, h2, Bv.z * dtu);
            h3 = fmaf(dA3, h3, Bv.w * dtu);
            float ys = h0 * Cv.x;
            ys = fmaf(h1, Cv.y, ys);
            ys = fmaf(h2, Cv.z, ys);
            ys = fmaf(h3, Cv.w, ys);
            ys += __shfl_xor_sync(0xffffffffu, ys, 1);
            ys += __shfl_xor_sync(0xffffffffu, ys, 2);
            if (g == 0) {
                float z = s_z[r][lcol];
                s_y[r][lcol] = (ys + Dd * uv) * (z / (1.f + __expf(-z)));
            }
        }
        __syncthreads();
        for (int i = tid; i < CH * 32; i += 128) {
            int r = i >> 5, cc = i & 31;
            yp16[(size_t)(b * L_SZ + c0 + r) * DI + d0 + cc] =
                __float2bfloat16_rn(s_y[r][cc]);
        }
    }
}

// ---------------------------------------------------------------------------
// kernel_launch
// ---------------------------------------------------------------------------
extern "C" void kernel_launch(void* const* d_in, const int* in_sizes, int n_in,
                              void* d_out, int out_size) {
    const float* x      = (const float*)d_in[0];
    const float* ln_g   = (const float*)d_in[1];
    const float* ln_b   = (const float*)d_in[2];
    const float* W_in   = (const float*)d_in[3];
    const float* conv_w = (const float*)d_in[4];
    const float* conv_b = (const float*)d_in[5];
    const float* W_x    = (const float*)d_in[6];
    const float* W_dt   = (const float*)d_in[7];
    const float* b_dt   = (const float*)d_in[8];
    const float* A_log  = (const float*)d_in[9];
    const float* Dp     = (const float*)d_in[10];
    const float* W_out  = (const float*)d_in[11];
    float* out = (float*)d_out;

    float *xz, *xc, *dbc, *dtb;
    __nv_bfloat16 *xn16, *xc16, *dbc16, *yp16, *wtin, *wtx, *wtdt, *wtout;
    cudaGetSymbolAddress((void**)&xz,    g_xz);
    cudaGetSymbolAddress((void**)&xc,    g_xc);
    cudaGetSymbolAddress((void**)&dbc,   g_dbc);
    cudaGetSymbolAddress((void**)&dtb,   g_dt);
    cudaGetSymbolAddress((void**)&xn16,  g_xn16);
    cudaGetSymbolAddress((void**)&xc16,  g_xc16);
    cudaGetSymbolAddress((void**)&dbc16, g_dbc16);
    cudaGetSymbolAddress((void**)&yp16,  g_yp16);
    cudaGetSymbolAddress((void**)&wtin,  g_wt_in);
    cudaGetSymbolAddress((void**)&wtx,   g_wt_x);
    cudaGetSymbolAddress((void**)&wtdt,  g_wt_dt);
    cudaGetSymbolAddress((void**)&wtout, g_wt_out);

    cudaFuncSetAttribute(mma_gemm<0,false>, cudaFuncAttributeMaxDynamicSharedMemorySize, GEMM_SMEM_BYTES);
    cudaFuncSetAttribute(mma_gemm<0,true >, cudaFuncAttributeMaxDynamicSharedMemorySize, GEMM_SMEM_BYTES);
    cudaFuncSetAttribute(mma_gemm<1,false>, cudaFuncAttributeMaxDynamicSharedMemorySize, GEMM_SMEM_BYTES);
    cudaFuncSetAttribute(mma_gemm<2,false>, cudaFuncAttributeMaxDynamicSharedMemorySize, GEMM_SMEM_BYTES);

    dim3 tb(32, 32);
    transpose_pad_kernel<<<dim3(1024 / 32, 4096 / 32), tb>>>(W_in, wtin, 1024, 4096);
    transpose_pad_kernel<<<dim3(2048 / 32, 128 / 32), tb>>>(W_x, wtx, 2048, 96);
    transpose_pad_kernel<<<dim3(64 / 32, 2048 / 32), tb>>>(W_dt, wtdt, 64, 2048);
    transpose_pad_kernel<<<dim3(2048 / 32, 1024 / 32), tb>>>(W_out, wtout, 2048, 1024);

    // 1. LayerNorm -> bf16
    ln_kernel<<<NROWS, 256>>>(x, ln_g, ln_b, xn16);

    // 2. xz = xn @ W_in   [8192,1024] x [1024,4096]  (fp32 out)
    mma_gemm<0,false><<<dim3(32, 64), 256, GEMM_SMEM_BYTES>>>(
        xn16, wtin, xz, nullptr, DM, DM, DM, 4096, 4096, nullptr);

    // 3. xc = silu(conv(xh)) -> fp32 + bf16
    conv_silu_kernel<<<(NROWS * DI) / 256, 256>>>(xz, conv_w, conv_b, xc, xc16);

    // 4. dbc = xc @ W_x  [8192,2048]x[2048,96] (N pad 128, store 96; dual out)
    mma_gemm<0,true><<<dim3(1, 64), 256, GEMM_SMEM_BYTES>>>(
        xc16, wtx, dbc, dbc16, DI, DI, DI, DBC_W, DBC_W, nullptr);

    // 5. dt = softplus(dbc[:, :64] @ W_dt + b_dt)  [8192,64] x [64,2048]
    mma_gemm<1,false><<<dim3(16, 64), 256, GEMM_SMEM_BYTES>>>(
        dbc16, wtdt, dtb, nullptr, DTR, DBC_W, DTR, DI, DI, b_dt);

    // 6. selective scan + (+D*u)*silu(z)  -> yp (bf16)
    scan_kernel<<<dim3(DI / 32, B_SZ), 128>>>(dtb, dbc, xc, xz, A_log, Dp, yp16);

    // 7. out = x + yp @ W_out   [8192,2048] x [2048,1024]
    mma_gemm<2,false><<<dim3(8, 64), 256, GEMM_SMEM_BYTES>>>(
        yp16, wtout, out, nullptr, DI, DI, DI, DM, DM, x);
}